// round 15
// baseline (speedup 1.0000x reference)
#include <cuda_runtime.h>
#include <cstdint>

#define NCOEF  81
#define NT     215
#define TPB    256
#define MTILE  128     // batch rows per CTA (8 warps x 16 rows)
#define NPAIR  45
#define XTS    129     // xT row stride (floats)
#define BRS    104     // staged-B row stride: 104 % 32 == 8 -> conflict-free b-frag loads
#define KCH    64      // K chunk (8 k-tiles of 8)
#define VRS    89      // V buffer row stride
#define MAXNT  11      // max n-tiles (Npad<=88)

// ---- smem float offsets ----
#define XT_OFF   0
#define BHI_OFF  10452              // 81*129=10449 -> pad 10452
#define BLO_OFF  (BHI_OFF + 6656)   // 64*104
#define VB_OFF   (BLO_OFF + 6656)
#define TBL_OFF  (VB_OFF + 11392)   // 128*89
#define SMEM_FL  (TBL_OFF + 640)    // 10*45 pair table + 2*88 n-map + slack

// ---------------------------------------------------------------------------
__device__ __forceinline__ void tf32_split(float v, unsigned& hi, unsigned& lo) {
    asm("cvt.rna.tf32.f32 %0, %1;" : "=r"(hi) : "f"(v));
    float r = v - __uint_as_float(hi);
    asm("cvt.rna.tf32.f32 %0, %1;" : "=r"(lo) : "f"(r));
}

__device__ __forceinline__ void mma_tf32(float (&c)[4], const unsigned (&a)[4],
                                         unsigned b0, unsigned b1) {
    asm volatile("mma.sync.aligned.m16n8k8.row.col.f32.tf32.tf32.f32 "
                 "{%0,%1,%2,%3}, {%4,%5,%6,%7}, {%8,%9}, {%0,%1,%2,%3};"
                 : "+f"(c[0]), "+f"(c[1]), "+f"(c[2]), "+f"(c[3])
                 : "r"(a[0]), "r"(a[1]), "r"(a[2]), "r"(a[3]), "r"(b0), "r"(b1));
}

// ---------------------------------------------------------------------------
extern __shared__ float smem_f[];

__global__ void __launch_bounds__(TPB, 1)
bispec_mma(const float* __restrict__ x, const float* __restrict__ cg,
           float* __restrict__ out, int B)
{
    float* xT  = smem_f + XT_OFF;    // [81][129] transposed x tile
    float* Bhi = smem_f + BHI_OFF;   // [64][104] staged C chunk (tf32 hi)
    float* Blo = smem_f + BLO_OFF;   // [64][104] (tf32 lo)
    float* Vb  = smem_f + VB_OFF;    // [128][89] GEMM result
    int*   tb  = (int*)(smem_f + TBL_OFF);
    int* p_l1s = tb;            int* p_l2s = tb + NPAIR;
    int* p_d2  = tb + 2*NPAIR;  int* p_K   = tb + 3*NPAIR;
    int* p_Nre = tb + 4*NPAIR;  int* p_Npd = tb + 5*NPAIR;
    int* p_T0  = tb + 6*NPAIR;  int* p_Ls  = tb + 7*NPAIR;
    int* p_Le  = tb + 8*NPAIR;
    unsigned* p_M2 = (unsigned*)(tb + 9*NPAIR);
    int* nTt = tb + 10*NPAIR;   // [88] n -> triple index
    int* nMm = nTt + 88;        // [88] n -> m within l-block

    const int tid  = threadIdx.x;
    const int lane = tid & 31;
    const int w    = tid >> 5;
    const int gid  = lane >> 2;     // 0..7
    const int tg   = lane & 3;      // 0..3
    const int b0   = blockIdx.x * MTILE;

    // ---- pair table (must match reference enumeration order) ----
    if (tid == 0) {
        int p = 0, t0 = 0;
        for (int l1 = 0; l1 <= 8; l1++)
            for (int l2 = l1; l2 <= 8; l2++) {
                int lstart = l2 - l1;
                int lend   = (l1 + l2 < 8) ? (l1 + l2) : 8;
                int d2 = 2*l2 + 1;
                p_l1s[p] = l1*l1; p_l2s[p] = l2*l2;
                p_d2[p] = d2; p_K[p] = (2*l1 + 1) * d2;
                int nre = (lend+1)*(lend+1) - lstart*lstart;
                p_Nre[p] = nre; p_Npd[p] = (nre + 7) & ~7;
                p_T0[p] = t0; p_Ls[p] = lstart; p_Le[p] = lend;
                // magic for /d2; d2==1 handled by branch at use site
                p_M2[p] = (unsigned)((0x100000000ULL + d2 - 1) / (unsigned)d2);
                t0 += lend - lstart + 1;
                p++;
            }
    }

    // ---- stage x tile transposed: xT[c][r] = x[b0+r][c] ----
    for (int idx = tid; idx < NCOEF * MTILE; idx += TPB) {
        int r = idx / NCOEF, c = idx - r * NCOEF;
        float v = (b0 + r < B) ? x[(size_t)b0 * NCOEF + idx] : 0.0f;
        xT[c * XTS + r] = v;
    }
    __syncthreads();

    for (int p = 0; p < NPAIR; p++) {
        const int l1s = p_l1s[p], l2s = p_l2s[p], d2 = p_d2[p], K = p_K[p];
        const int Nreal = p_Nre[p], Npad = p_Npd[p], t0 = p_T0[p];
        const int lstart = p_Ls[p], lend = p_Le[p];
        const unsigned m2 = p_M2[p];
        const bool d2one = (d2 == 1);
        const int ntiles = Npad >> 3;
        const unsigned mN = (unsigned)((0x100000000ULL + Npad - 1) / (unsigned)Npad);

        // n -> (triple, m) map
        if (tid < Npad) {
            int m = tid, l = lstart;
            while (l < lend && m >= 2*l + 1) { m -= 2*l + 1; l++; }
            nTt[tid] = t0 + (l - lstart);
            nMm[tid] = m;
        }
        __syncthreads();

        // accumulators: 11 n-tiles x 4 fp32 (guarded unrolled access)
        float acc[MAXNT][4];
#pragma unroll
        for (int nt = 0; nt < MAXNT; nt++) {
            acc[nt][0] = 0.f; acc[nt][1] = 0.f; acc[nt][2] = 0.f; acc[nt][3] = 0.f;
        }

        const int nch = (K + KCH - 1) / KCH;
        const int rA0 = w * 16 + gid;

        for (int kc = 0; kc < nch; kc++) {
            // ---- stage B chunk: B[kk][n] = C[t(n)][i(kg)][j(kg)][m(n)], hi/lo ----
            const int total = Npad << 6;          // Npad * 64
            for (int e = tid; e < total; e += TPB) {
                int kk = (int)__umulhi((unsigned)e, mN);
                int n  = e - kk * Npad;
                int kg = kc * KCH + kk;
                float v = 0.0f;
                if (n < Nreal && kg < K) {
                    int i = d2one ? kg : (int)__umulhi((unsigned)kg, m2);
                    int j = kg - i * d2;
                    v = cg[(size_t)nTt[n] * 4913 + i * 289 + j * 17 + nMm[n]];
                }
                unsigned hb, lb;
                tf32_split(v, hb, lb);
                Bhi[kk * BRS + n] = __uint_as_float(hb);
                Blo[kk * BRS + n] = __uint_as_float(lb);
            }
            __syncthreads();

            const int krem = K - kc * KCH;
            const int ktn  = (krem >= KCH) ? 8 : ((krem + 7) >> 3);

            for (int kt = 0; kt < ktn; kt++) {
                // ---- build A fragments from xT (P = F1_i * F2_j), 3xTF32 split ----
                const int kg0 = kc * KCH + kt * 8 + tg;
                const int kg1 = kg0 + 4;
                float p00 = 0.f, p01 = 0.f, p10 = 0.f, p11 = 0.f;
                if (kg0 < K) {
                    int i = d2one ? kg0 : (int)__umulhi((unsigned)kg0, m2);
                    int j = kg0 - i * d2;
                    const float* c1 = xT + (l1s + i) * XTS;
                    const float* c2 = xT + (l2s + j) * XTS;
                    p00 = c1[rA0]     * c2[rA0];
                    p01 = c1[rA0 + 8] * c2[rA0 + 8];
                }
                if (kg1 < K) {
                    int i = d2one ? kg1 : (int)__umulhi((unsigned)kg1, m2);
                    int j = kg1 - i * d2;
                    const float* c1 = xT + (l1s + i) * XTS;
                    const float* c2 = xT + (l2s + j) * XTS;
                    p10 = c1[rA0]     * c2[rA0];
                    p11 = c1[rA0 + 8] * c2[rA0 + 8];
                }
                unsigned ah[4], al[4];
                tf32_split(p00, ah[0], al[0]);   // a0: (row gid,   k tg)
                tf32_split(p01, ah[1], al[1]);   // a1: (row gid+8, k tg)
                tf32_split(p10, ah[2], al[2]);   // a2: (row gid,   k tg+4)
                tf32_split(p11, ah[3], al[3]);   // a3: (row gid+8, k tg+4)

                const float* bh = Bhi + (kt * 8 + tg) * BRS;
                const float* bl = Blo + (kt * 8 + tg) * BRS;
#pragma unroll
                for (int nt = 0; nt < MAXNT; nt++) {
                    if (nt < ntiles) {
                        int nn = nt * 8 + gid;
                        unsigned bh0 = __float_as_uint(bh[nn]);
                        unsigned bh1 = __float_as_uint(bh[4 * BRS + nn]);
                        unsigned bl0 = __float_as_uint(bl[nn]);
                        unsigned bl1 = __float_as_uint(bl[4 * BRS + nn]);
                        mma_tf32(acc[nt], ah, bh0, bh1);   // hi*hi
                        mma_tf32(acc[nt], ah, bl0, bl1);   // hi*lo
                        mma_tf32(acc[nt], al, bh0, bh1);   // lo*hi
                    }
                }
            }
            __syncthreads();   // B buffer safe for restage
        }

        // ---- epilogue: fragments -> Vb ----
#pragma unroll
        for (int nt = 0; nt < MAXNT; nt++) {
            if (nt < ntiles) {
                int c0 = nt * 8 + 2 * tg;
                Vb[rA0 * VRS + c0]           = acc[nt][0];
                Vb[rA0 * VRS + c0 + 1]       = acc[nt][1];
                Vb[(rA0 + 8) * VRS + c0]     = acc[nt][2];
                Vb[(rA0 + 8) * VRS + c0 + 1] = acc[nt][3];
            }
        }
        __syncthreads();

        // ---- fold with F3 and store ----
        if (tid < MTILE && b0 + tid < B) {
            const float* vr = Vb + tid * VRS;
            size_t ob = (size_t)(b0 + tid) * NT + t0;
            int no = 0;
            for (int l = lstart; l <= lend; l++) {
                int dl = 2*l + 1, lsq = l*l;
                float s = 0.0f;
                for (int m = 0; m < dl; m++)
                    s += xT[(lsq + m) * XTS + tid] * vr[no + m];
                out[ob + (l - lstart)] = s;
                no += dl;
            }
        }
        __syncthreads();   // Vb / nT tables safe for next pair
    }
}

// ---------------------------------------------------------------------------
extern "C" void kernel_launch(void* const* d_in, const int* in_sizes, int n_in,
                              void* d_out, int out_size)
{
    const float* x  = (const float*)d_in[0];
    const float* cg = (const float*)d_in[1];
    float* out = (float*)d_out;

    int B = in_sizes[0] / NCOEF;
    int grid = (B + MTILE - 1) / MTILE;

    size_t smem_bytes = (size_t)SMEM_FL * sizeof(float);   // ~143 KB

    cudaFuncSetAttribute(bispec_mma,
                         cudaFuncAttributeMaxDynamicSharedMemorySize,
                         (int)smem_bytes);

    bispec_mma<<<grid, TPB, smem_bytes>>>(x, cg, out, B);
}

// round 16
// speedup vs baseline: 1.4602x; 1.4602x over previous
#include <cuda_runtime.h>
#include <cstdint>

#define NCOEF  81
#define NT     215
#define TPB    256
#define MTILE  128     // batch rows per CTA (8 warps x m16)
#define NPAIR  45
#define XTS    129     // xT row stride (floats)
#define MAXNT  11      // max n-tiles (Npad <= 88)
#define CELLW  44      // floats per (kt,lane) cell = MAXNT*4; stride 44 -> conflict-free LDS.128
#define VRS    89      // V buffer row stride
#define KCH    64      // K chunk (8 k-tiles of 8)

// ---- smem float offsets ----
#define XT_OFF   0
#define BF_OFF   10452                    // 81*129=10449 -> pad to 10452 (16B aligned)
#define VB_OFF   (BF_OFF + 8*32*CELLW)    // + 11264
#define TBL_OFF  (VB_OFF + 128*VRS)       // + 11392
#define SMEM_FL  (TBL_OFF + 1200)         // tables: 450 + 88 + 292 + 292 + slack

// ---------------------------------------------------------------------------
__device__ __forceinline__ void tf32_split(float v, unsigned& hi, unsigned& lo) {
    asm("cvt.rna.tf32.f32 %0, %1;" : "=r"(hi) : "f"(v));
    float r = v - __uint_as_float(hi);
    asm("cvt.rna.tf32.f32 %0, %1;" : "=r"(lo) : "f"(r));
}

__device__ __forceinline__ void mma_tf32(float (&c)[4], const unsigned (&a)[4],
                                         unsigned b0, unsigned b1) {
    asm volatile("mma.sync.aligned.m16n8k8.row.col.f32.tf32.tf32.f32 "
                 "{%0,%1,%2,%3}, {%4,%5,%6,%7}, {%8,%9}, {%0,%1,%2,%3};"
                 : "+f"(c[0]), "+f"(c[1]), "+f"(c[2]), "+f"(c[3])
                 : "r"(a[0]), "r"(a[1]), "r"(a[2]), "r"(a[3]), "r"(b0), "r"(b1));
}

// ---------------------------------------------------------------------------
extern __shared__ float smem_f[];

__global__ void __launch_bounds__(TPB, 1)
bispec_mma(const float* __restrict__ x, const float* __restrict__ cg,
           float* __restrict__ out, int B)
{
    float* xT = smem_f + XT_OFF;   // [81][129] transposed x tile
    float* Bf = smem_f + BF_OFF;   // fragment-packed B: [8 kt][32 lane][MAXNT][4]
    float* Vb = smem_f + VB_OFF;   // [128][89] GEMM result
    int*   tb = (int*)(smem_f + TBL_OFF);
    int* p_l1s = tb;            int* p_l2s = tb + NPAIR;
    int* p_d2  = tb + 2*NPAIR;  int* p_K   = tb + 3*NPAIR;
    int* p_Nre = tb + 4*NPAIR;  int* p_Npd = tb + 5*NPAIR;
    int* p_T0  = tb + 6*NPAIR;  int* p_Ls  = tb + 7*NPAIR;
    int* p_Le  = tb + 8*NPAIR;
    unsigned* p_M2 = (unsigned*)(tb + 9*NPAIR);
    int* nOff = tb + 10*NPAIR;        // [88]  n -> cg offset (triple*4913 + m)
    int* ktab = nOff + 88;            // [292] k -> i*289 + j*17
    unsigned* kxy = (unsigned*)(ktab + 292);  // [292] packed xT row offsets

    const int tid  = threadIdx.x;
    const int lane = tid & 31;
    const int w    = tid >> 5;
    const int gid  = lane >> 2;     // 0..7
    const int tg   = lane & 3;      // 0..3
    const int b0   = blockIdx.x * MTILE;
    const int rA0  = w * 16 + gid;

    // ---- pair table (must match reference enumeration order) ----
    if (tid == 0) {
        int p = 0, t0 = 0;
        for (int l1 = 0; l1 <= 8; l1++)
            for (int l2 = l1; l2 <= 8; l2++) {
                int lstart = l2 - l1;
                int lend   = (l1 + l2 < 8) ? (l1 + l2) : 8;
                int d2 = 2*l2 + 1;
                p_l1s[p] = l1*l1; p_l2s[p] = l2*l2;
                p_d2[p] = d2; p_K[p] = (2*l1 + 1) * d2;
                int nre = (lend+1)*(lend+1) - lstart*lstart;
                p_Nre[p] = nre; p_Npd[p] = (nre + 7) & ~7;
                p_T0[p] = t0; p_Ls[p] = lstart; p_Le[p] = lend;
                p_M2[p] = (unsigned)((0x100000000ULL + d2 - 1) / (unsigned)d2);
                t0 += lend - lstart + 1;
                p++;
            }
    }

    // ---- stage x tile transposed: xT[c][r] = x[b0+r][c] ----
    for (int idx = tid; idx < NCOEF * MTILE; idx += TPB) {
        int r = idx / NCOEF, c = idx - r * NCOEF;
        float v = (b0 + r < B) ? x[(size_t)b0 * NCOEF + idx] : 0.0f;
        xT[c * XTS + r] = v;
    }
    __syncthreads();

    for (int p = 0; p < NPAIR; p++) {
        const int l1s = p_l1s[p], l2s = p_l2s[p], d2 = p_d2[p], K = p_K[p];
        const int Nreal = p_Nre[p], Npad = p_Npd[p], t0 = p_T0[p];
        const int lstart = p_Ls[p], lend = p_Le[p];
        const unsigned m2 = p_M2[p];
        const bool d2one = (d2 == 1);
        const int ntiles = Npad >> 3;

        // ---- per-pair lookup tables (kill divides in hot loops) ----
        for (int k = tid; k < K; k += TPB) {
            int i = d2one ? k : (int)__umulhi((unsigned)k, m2);
            int j = k - i * d2;
            ktab[k] = i * 289 + j * 17;
            kxy[k]  = ((unsigned)((l1s + i) * XTS) << 16) | (unsigned)((l2s + j) * XTS);
        }
        if (tid < Npad) {
            int m = tid, l = lstart;
            while (l < lend && m >= 2*l + 1) { m -= 2*l + 1; l++; }
            nOff[tid] = (t0 + (l - lstart)) * 4913 + m;
        }
        __syncthreads();

        float acc[MAXNT][4];
#pragma unroll
        for (int nt = 0; nt < MAXNT; nt++) {
            acc[nt][0] = 0.f; acc[nt][1] = 0.f; acc[nt][2] = 0.f; acc[nt][3] = 0.f;
        }

        const int nch = (K + KCH - 1) / KCH;
        for (int kc = 0; kc < nch; kc++) {
            // ---- stage fragment-packed B chunk ----
            // cell c -> (nt = c>>8, klane = c&255); lane2=klane&31, kt=klane>>5
            for (int c = tid; c < (ntiles << 8); c += TPB) {
                int nt    = c >> 8;
                int klane = c & 255;
                int lane2 = klane & 31, kt = klane >> 5;
                int tg2 = lane2 & 3, gid2 = lane2 >> 2;
                int n  = nt * 8 + gid2;
                int k0 = kc * KCH + kt * 8 + tg2;
                float v0 = 0.f, v1 = 0.f;
                if (n < Nreal) {
                    int nof = nOff[n];
                    if (k0 < K)     v0 = cg[nof + ktab[k0]];
                    if (k0 + 4 < K) v1 = cg[nof + ktab[k0 + 4]];
                }
                unsigned h0, l0, h1, l1;
                tf32_split(v0, h0, l0);
                tf32_split(v1, h1, l1);
                float4 f4;
                f4.x = __uint_as_float(h0); f4.y = __uint_as_float(h1);
                f4.z = __uint_as_float(l0); f4.w = __uint_as_float(l1);
                *(float4*)(Bf + klane * CELLW + nt * 4) = f4;
            }
            __syncthreads();

            const int krem = K - kc * KCH;
            const int ktn  = (krem >= KCH) ? 8 : ((krem + 7) >> 3);

            for (int kt = 0; kt < ktn; kt++) {
                // ---- A fragments from xT via packed row-offset table ----
                const int kg0 = kc * KCH + kt * 8 + tg;
                const int kg1 = kg0 + 4;
                float p00 = 0.f, p01 = 0.f, p10 = 0.f, p11 = 0.f;
                if (kg0 < K) {
                    unsigned pk = kxy[kg0];
                    const float* c1 = xT + (pk >> 16);
                    const float* c2 = xT + (pk & 0xFFFFu);
                    p00 = c1[rA0]     * c2[rA0];
                    p01 = c1[rA0 + 8] * c2[rA0 + 8];
                }
                if (kg1 < K) {
                    unsigned pk = kxy[kg1];
                    const float* c1 = xT + (pk >> 16);
                    const float* c2 = xT + (pk & 0xFFFFu);
                    p10 = c1[rA0]     * c2[rA0];
                    p11 = c1[rA0 + 8] * c2[rA0 + 8];
                }
                unsigned ah[4], al[4];
                tf32_split(p00, ah[0], al[0]);
                tf32_split(p01, ah[1], al[1]);
                tf32_split(p10, ah[2], al[2]);
                tf32_split(p11, ah[3], al[3]);

                const float* cell = Bf + (kt * 32 + lane) * CELLW;
#pragma unroll
                for (int nt = 0; nt < MAXNT; nt++) {
                    if (nt < ntiles) {
                        float4 b4 = *(const float4*)(cell + nt * 4);
                        unsigned bh0 = __float_as_uint(b4.x);
                        unsigned bh1 = __float_as_uint(b4.y);
                        unsigned bl0 = __float_as_uint(b4.z);
                        unsigned bl1 = __float_as_uint(b4.w);
                        mma_tf32(acc[nt], ah, bh0, bh1);   // hi*hi
                        mma_tf32(acc[nt], ah, bl0, bl1);   // hi*lo
                        mma_tf32(acc[nt], al, bh0, bh1);   // lo*hi
                    }
                }
            }
            __syncthreads();   // Bf safe for restage
        }

        // ---- epilogue: fragments -> Vb ----
#pragma unroll
        for (int nt = 0; nt < MAXNT; nt++) {
            if (nt < ntiles) {
                int c0 = nt * 8 + 2 * tg;
                Vb[rA0 * VRS + c0]           = acc[nt][0];
                Vb[rA0 * VRS + c0 + 1]       = acc[nt][1];
                Vb[(rA0 + 8) * VRS + c0]     = acc[nt][2];
                Vb[(rA0 + 8) * VRS + c0 + 1] = acc[nt][3];
            }
        }
        __syncthreads();

        // ---- fold with F3 and store ----
        if (tid < MTILE && b0 + tid < B) {
            const float* vr = Vb + tid * VRS;
            size_t ob = (size_t)(b0 + tid) * NT + t0;
            int no = 0;
            for (int l = lstart; l <= lend; l++) {
                int dl = 2*l + 1, lsq = l*l;
                float s = 0.0f;
                for (int m = 0; m < dl; m++)
                    s += xT[(lsq + m) * XTS + tid] * vr[no + m];
                out[ob + (l - lstart)] = s;
                no += dl;
            }
        }
        __syncthreads();   // Vb / tables safe for next pair
    }
}

// ---------------------------------------------------------------------------
extern "C" void kernel_launch(void* const* d_in, const int* in_sizes, int n_in,
                              void* d_out, int out_size)
{
    const float* x  = (const float*)d_in[0];
    const float* cg = (const float*)d_in[1];
    float* out = (float*)d_out;

    int B = in_sizes[0] / NCOEF;
    int grid = (B + MTILE - 1) / MTILE;

    size_t smem_bytes = (size_t)SMEM_FL * sizeof(float);   // ~138 KB

    cudaFuncSetAttribute(bispec_mma,
                         cudaFuncAttributeMaxDynamicSharedMemorySize,
                         (int)smem_bytes);

    bispec_mma<<<grid, TPB, smem_bytes>>>(x, cg, out, B);
}

// round 17
// speedup vs baseline: 1.9371x; 1.3266x over previous
#include <cuda_runtime.h>
#include <cstdint>

#define NCOEF  81
#define NT     215
#define TPB    256
#define MTILE  128     // batch rows per CTA (8 warps x m16)
#define NPAIR  45
#define XTS    129     // xT row stride (floats)
#define MAXNT  11      // max n-tiles (Npad <= 88)
#define CELLW  44      // floats per (kt,lane) cell; stride 44 -> conflict-free LDS.128
#define VRS    89      // V buffer row stride
#define KCH    64      // K chunk (8 k-tiles of 8)

// ---- main-kernel smem float offsets ----
#define XT_OFF   0
#define BF0_OFF  10452                    // 81*129=10449 -> pad (16B aligned)
#define BF1_OFF  (BF0_OFF + 11264)        // 8*32*CELLW
#define VB_OFF   (BF1_OFF + 11264)
#define TBL_OFF  (VB_OFF + 128*VRS)
#define SMEM_FL  (TBL_OFF + 800)          // ~180.7 KB total

// Precomputed fragment-packed tf32-split B for all (pair, chunk):
// sum over pairs of nch*ntiles*1024 floats = 690,176
__device__ float g_bsplit[700000];

// ---------------------------------------------------------------------------
__device__ __forceinline__ void tf32_split(float v, unsigned& hi, unsigned& lo) {
    asm("cvt.rna.tf32.f32 %0, %1;" : "=r"(hi) : "f"(v));
    float r = v - __uint_as_float(hi);
    asm("cvt.rna.tf32.f32 %0, %1;" : "=r"(lo) : "f"(r));
}

__device__ __forceinline__ void mma_tf32(float (&c)[4], const unsigned (&a)[4],
                                         unsigned b0, unsigned b1) {
    asm volatile("mma.sync.aligned.m16n8k8.row.col.f32.tf32.tf32.f32 "
                 "{%0,%1,%2,%3}, {%4,%5,%6,%7}, {%8,%9}, {%0,%1,%2,%3};"
                 : "+f"(c[0]), "+f"(c[1]), "+f"(c[2]), "+f"(c[3])
                 : "r"(a[0]), "r"(a[1]), "r"(a[2]), "r"(a[3]), "r"(b0), "r"(b1));
}

__device__ __forceinline__ unsigned smem_u32(const void* p) {
    unsigned r;
    asm("{ .reg .u64 t; cvta.to.shared.u64 t, %1; cvt.u32.u64 %0, t; }"
        : "=r"(r) : "l"(p));
    return r;
}

__device__ __forceinline__ void cp_async16(unsigned dst, const float* src) {
    asm volatile("cp.async.ca.shared.global [%0], [%1], 16;" :: "r"(dst), "l"(src));
}
#define CP_COMMIT() asm volatile("cp.async.commit_group;" ::: "memory")
#define CP_WAIT1()  asm volatile("cp.async.wait_group 1;" ::: "memory")
#define CP_WAIT0()  asm volatile("cp.async.wait_group 0;" ::: "memory")

// ---------------------------------------------------------------------------
// Prep kernel: one CTA per (l1,l2) pair. Builds the tf32-split,
// fragment-packed B for every K-chunk of its pair into g_bsplit.
// Chunk layout: cell (nt, klane) at (nt*256 + klane)*4 floats (coalesced).
// ---------------------------------------------------------------------------
__global__ void __launch_bounds__(TPB, 1)
prep_bsplit(const float* __restrict__ cg)
{
    __shared__ int ktab[292];   // k -> i*289 + j*17
    __shared__ int nOff[88];    // n -> triple*4913 + m
    __shared__ int sP[8];       // K, Nreal, Npad, gbase, d2, lstart, lend, t0

    const int tid = threadIdx.x;
    const int p   = blockIdx.x;

    if (tid == 0) {
        int pp = 0, t0 = 0, gb = 0;
        for (int l1 = 0; l1 <= 8; l1++)
            for (int l2 = l1; l2 <= 8; l2++) {
                int lstart = l2 - l1;
                int lend   = (l1 + l2 < 8) ? (l1 + l2) : 8;
                int d2 = 2*l2 + 1;
                int K  = (2*l1 + 1) * d2;
                int nre  = (lend+1)*(lend+1) - lstart*lstart;
                int npd  = (nre + 7) & ~7;
                int nch  = (K + KCH - 1) / KCH;
                if (pp == p) {
                    sP[0] = K; sP[1] = nre; sP[2] = npd; sP[3] = gb;
                    sP[4] = d2; sP[5] = lstart; sP[6] = lend; sP[7] = t0;
                }
                gb += nch * (npd >> 3) * 1024;
                t0 += lend - lstart + 1;
                pp++;
            }
    }
    __syncthreads();
    const int K = sP[0], Nreal = sP[1], Npad = sP[2], gb = sP[3];
    const int d2 = sP[4], lstart = sP[5], lend = sP[6], t0 = sP[7];
    const int ntiles = Npad >> 3;
    const int nch = (K + KCH - 1) / KCH;

    for (int k = tid; k < K; k += TPB) {
        int i = k / d2, j = k - i * d2;
        ktab[k] = i * 289 + j * 17;
    }
    if (tid < Npad) {
        int m = tid, l = lstart;
        while (l < lend && m >= 2*l + 1) { m -= 2*l + 1; l++; }
        nOff[tid] = (t0 + (l - lstart)) * 4913 + m;
    }
    __syncthreads();

    const int lane2 = tid & 31, kt = tid >> 5;   // tid == klane (256 threads)
    const int tg2 = lane2 & 3, gid2 = lane2 >> 2;

    for (int kc = 0; kc < nch; kc++) {
        float* gout = g_bsplit + gb + kc * (ntiles << 10);
        for (int nt = 0; nt < ntiles; nt++) {
            int n  = nt * 8 + gid2;
            int k0 = kc * KCH + kt * 8 + tg2;
            float v0 = 0.f, v1 = 0.f;
            if (n < Nreal) {
                int nof = nOff[n];
                if (k0 < K)     v0 = cg[nof + ktab[k0]];
                if (k0 + 4 < K) v1 = cg[nof + ktab[k0 + 4]];
            }
            unsigned h0, l0, h1, l1;
            tf32_split(v0, h0, l0);
            tf32_split(v1, h1, l1);
            float4 f4;
            f4.x = __uint_as_float(h0); f4.y = __uint_as_float(h1);
            f4.z = __uint_as_float(l0); f4.w = __uint_as_float(l1);
            *(float4*)(gout + ((nt << 8) + tid) * 4) = f4;   // coalesced
        }
    }
}

// ---------------------------------------------------------------------------
// Main kernel: per-pair V = P * C^T via mma.sync tf32 (3x split), B streamed
// from g_bsplit with double-buffered cp.async.
// ---------------------------------------------------------------------------
extern __shared__ float smem_f[];

__global__ void __launch_bounds__(TPB, 1)
bispec_mma(const float* __restrict__ x, float* __restrict__ out, int B)
{
    float* xT = smem_f + XT_OFF;
    float* Vb = smem_f + VB_OFF;
    int*   tb = (int*)(smem_f + TBL_OFF);
    int* p_l1s = tb;            int* p_l2s = tb + NPAIR;
    int* p_d2  = tb + 2*NPAIR;  int* p_K   = tb + 3*NPAIR;
    int* p_Npd = tb + 4*NPAIR;  int* p_T0  = tb + 5*NPAIR;
    int* p_Ls  = tb + 6*NPAIR;  int* p_Le  = tb + 7*NPAIR;
    int* p_GB  = tb + 8*NPAIR;
    unsigned* p_M2 = (unsigned*)(tb + 9*NPAIR);
    unsigned* kxy  = (unsigned*)(tb + 10*NPAIR);   // [292] packed xT row offsets

    const int tid  = threadIdx.x;
    const int lane = tid & 31;
    const int w    = tid >> 5;
    const int gid  = lane >> 2;
    const int tg   = lane & 3;
    const int b0   = blockIdx.x * MTILE;
    const int rA0  = w * 16 + gid;

    const unsigned bfs0 = smem_u32(smem_f + BF0_OFF);
    const unsigned bfs1 = smem_u32(smem_f + BF1_OFF);
    float* bff[2] = { smem_f + BF0_OFF, smem_f + BF1_OFF };

    if (tid == 0) {
        int p = 0, t0 = 0, gb = 0;
        for (int l1 = 0; l1 <= 8; l1++)
            for (int l2 = l1; l2 <= 8; l2++) {
                int lstart = l2 - l1;
                int lend   = (l1 + l2 < 8) ? (l1 + l2) : 8;
                int d2 = 2*l2 + 1;
                int K  = (2*l1 + 1) * d2;
                int nre = (lend+1)*(lend+1) - lstart*lstart;
                int npd = (nre + 7) & ~7;
                int nch = (K + KCH - 1) / KCH;
                p_l1s[p] = l1*l1; p_l2s[p] = l2*l2;
                p_d2[p] = d2; p_K[p] = K; p_Npd[p] = npd;
                p_T0[p] = t0; p_Ls[p] = lstart; p_Le[p] = lend;
                p_GB[p] = gb;
                p_M2[p] = (unsigned)((0x100000000ULL + d2 - 1) / (unsigned)d2);
                gb += nch * (npd >> 3) * 1024;
                t0 += lend - lstart + 1;
                p++;
            }
    }

    for (int idx = tid; idx < NCOEF * MTILE; idx += TPB) {
        int r = idx / NCOEF, c = idx - r * NCOEF;
        float v = (b0 + r < B) ? x[(size_t)b0 * NCOEF + idx] : 0.0f;
        xT[c * XTS + r] = v;
    }
    __syncthreads();

    for (int p = 0; p < NPAIR; p++) {
        const int l1s = p_l1s[p], l2s = p_l2s[p], d2 = p_d2[p], K = p_K[p];
        const int Npad = p_Npd[p], t0 = p_T0[p];
        const int lstart = p_Ls[p], lend = p_Le[p];
        const unsigned m2 = p_M2[p];
        const bool d2one = (d2 == 1);
        const int ntiles = Npad >> 3;
        const int nch = (K + KCH - 1) / KCH;
        const float* gsrc = g_bsplit + p_GB[p];
        const int chunkFl = ntiles << 10;

        for (int k = tid; k < K; k += TPB) {
            int i = d2one ? k : (int)__umulhi((unsigned)k, m2);
            int j = k - i * d2;
            kxy[k] = ((unsigned)((l1s + i) * XTS) << 16) | (unsigned)((l2s + j) * XTS);
        }
        __syncthreads();

        float acc[MAXNT][4];
#pragma unroll
        for (int nt = 0; nt < MAXNT; nt++) {
            acc[nt][0] = 0.f; acc[nt][1] = 0.f; acc[nt][2] = 0.f; acc[nt][3] = 0.f;
        }

        // prefetch chunk 0 into buf 0
        {
            const float* src = gsrc;
            unsigned dst = bfs0 + (unsigned)(tid * CELLW) * 4u;
            for (int nt = 0; nt < ntiles; nt++)
                cp_async16(dst + (unsigned)(nt << 4),
                           src + (((nt << 8) + tid) << 2));
            CP_COMMIT();
        }

        for (int kc = 0; kc < nch; kc++) {
            const int buf = kc & 1;
            const bool has_next = (kc + 1 < nch);
            if (has_next) {
                const float* src = gsrc + (kc + 1) * chunkFl;
                unsigned dst = (buf ? bfs0 : bfs1) + (unsigned)(tid * CELLW) * 4u;
                for (int nt = 0; nt < ntiles; nt++)
                    cp_async16(dst + (unsigned)(nt << 4),
                               src + (((nt << 8) + tid) << 2));
                CP_COMMIT();
                CP_WAIT1();
            } else {
                CP_WAIT0();
            }
            __syncthreads();   // chunk kc resident for all threads

            const float* Bf = bff[buf];
            const int krem = K - kc * KCH;
            const int ktn  = (krem >= KCH) ? 8 : ((krem + 7) >> 3);

            for (int kt = 0; kt < ktn; kt++) {
                const int kg0 = kc * KCH + kt * 8 + tg;
                const int kg1 = kg0 + 4;
                float p00 = 0.f, p01 = 0.f, p10 = 0.f, p11 = 0.f;
                if (kg0 < K) {
                    unsigned pk = kxy[kg0];
                    const float* c1 = xT + (pk >> 16);
                    const float* c2 = xT + (pk & 0xFFFFu);
                    p00 = c1[rA0]     * c2[rA0];
                    p01 = c1[rA0 + 8] * c2[rA0 + 8];
                }
                if (kg1 < K) {
                    unsigned pk = kxy[kg1];
                    const float* c1 = xT + (pk >> 16);
                    const float* c2 = xT + (pk & 0xFFFFu);
                    p10 = c1[rA0]     * c2[rA0];
                    p11 = c1[rA0 + 8] * c2[rA0 + 8];
                }
                unsigned ah[4], al[4];
                tf32_split(p00, ah[0], al[0]);
                tf32_split(p01, ah[1], al[1]);
                tf32_split(p10, ah[2], al[2]);
                tf32_split(p11, ah[3], al[3]);

                const float* cell = Bf + (kt * 32 + lane) * CELLW;
#pragma unroll
                for (int nt = 0; nt < MAXNT; nt++) {
                    if (nt < ntiles) {
                        float4 b4 = *(const float4*)(cell + nt * 4);
                        unsigned bh0 = __float_as_uint(b4.x);
                        unsigned bh1 = __float_as_uint(b4.y);
                        unsigned bl0 = __float_as_uint(b4.z);
                        unsigned bl1 = __float_as_uint(b4.w);
                        mma_tf32(acc[nt], ah, bh0, bh1);   // hi*hi
                        mma_tf32(acc[nt], ah, bl0, bl1);   // hi*lo
                        mma_tf32(acc[nt], al, bh0, bh1);   // lo*hi
                    }
                }
            }
            __syncthreads();   // all MMAs done before buf is overwritten
        }

        // ---- epilogue: fragments -> Vb ----
#pragma unroll
        for (int nt = 0; nt < MAXNT; nt++) {
            if (nt < ntiles) {
                int c0 = nt * 8 + 2 * tg;
                Vb[rA0 * VRS + c0]           = acc[nt][0];
                Vb[rA0 * VRS + c0 + 1]       = acc[nt][1];
                Vb[(rA0 + 8) * VRS + c0]     = acc[nt][2];
                Vb[(rA0 + 8) * VRS + c0 + 1] = acc[nt][3];
            }
        }
        __syncthreads();

        // ---- fold with F3 and store ----
        if (tid < MTILE && b0 + tid < B) {
            const float* vr = Vb + tid * VRS;
            size_t ob = (size_t)(b0 + tid) * NT + t0;
            int no = 0;
            for (int l = lstart; l <= lend; l++) {
                int dl = 2*l + 1, lsq = l*l;
                float s = 0.0f;
                for (int m = 0; m < dl; m++)
                    s += xT[(lsq + m) * XTS + tid] * vr[no + m];
                out[ob + (l - lstart)] = s;
                no += dl;
            }
        }
        __syncthreads();
    }
}

// ---------------------------------------------------------------------------
extern "C" void kernel_launch(void* const* d_in, const int* in_sizes, int n_in,
                              void* d_out, int out_size)
{
    const float* x  = (const float*)d_in[0];
    const float* cg = (const float*)d_in[1];
    float* out = (float*)d_out;

    int B = in_sizes[0] / NCOEF;
    int grid = (B + MTILE - 1) / MTILE;

    prep_bsplit<<<NPAIR, TPB>>>(cg);

    size_t smem_bytes = (size_t)SMEM_FL * sizeof(float);   // ~180.7 KB
    cudaFuncSetAttribute(bispec_mma,
                         cudaFuncAttributeMaxDynamicSharedMemorySize,
                         (int)smem_bytes);
    bispec_mma<<<grid, TPB, smem_bytes>>>(x, out, B);
}